// round 14
// baseline (speedup 1.0000x reference)
#include <cuda_runtime.h>
#include <math.h>
#include <float.h>

#define BATCH   256
#define NLEV    4
#define CDIM    8000
#define NTOTAL  10500
#define THREADS 512

// Packed accumulator: bits [0,48) fixed-point sum (x 2^32, all p >= 0),
// bits [48,..) arrival count. Integer adds commute exactly -> deterministic.
__device__ unsigned long long g_acc = 0ULL;

__device__ __forceinline__ void amax_comb(float& av, int& ai, float av2, int ai2) {
    if (av2 > av || (av2 == av && ai2 < ai)) { av = av2; ai = ai2; }
}

// FMA-pipe exp (no MUFU). Rel err <= ~5e-5; inputs clamped to >= -80.
__device__ __forceinline__ float fexp_poly(float x) {
    float t = fmaxf(x, -80.0f) * 1.4426950408889634f;
    float r = t + 12582912.0f;
    int   k = __float_as_int(r) - 0x4B400000;
    float f = t - (r - 12582912.0f);
    float p = 0.009618129107f;
    p = fmaf(p, f, 0.055504108664f);
    p = fmaf(p, f, 0.240226506959f);
    p = fmaf(p, f, 0.693147180560f);
    p = fmaf(p, f, 1.0f);
    return __int_as_float(__float_as_int(p) + (k << 23));
}

// Exp-sum + argmax over one level's prefix (N4 float4s); loads issued up-front.
// Even batches MUFU __expf, odd batches FMA-pipe poly (dual-issue).
template<int N4, int STRIDE, int ITERS, bool NEED_SUM>
__device__ __forceinline__ void accum(const float4* __restrict__ row4, int lt,
                                      float& s, float& av, int& ai) {
    float4 v[ITERS]; int id[ITERS]; bool p[ITERS];
    #pragma unroll
    for (int k = 0; k < ITERS; k++) {
        int idx = lt + k * STRIDE;
        p[k]  = idx < N4;
        id[k] = p[k] ? idx : (N4 - 1);
        v[k]  = __ldg(&row4[id[k]]);
    }
    float s0 = 0.f, s1 = 0.f, s2 = 0.f, s3 = 0.f;
    float a0 = -FLT_MAX, a1 = -FLT_MAX, a2 = -FLT_MAX, a3 = -FLT_MAX;
    int   i0 = 0x7fffffff, i1 = 0x7fffffff, i2 = 0x7fffffff, i3 = 0x7fffffff;
    #pragma unroll
    for (int k = 0; k < ITERS; k++) {
        float4 w = v[k];
        if (!p[k]) { w.x = w.y = w.z = w.w = -FLT_MAX; }
        int e = 4 * id[k];
        if (NEED_SUM) {
            if ((k & 1) == 0) {
                s0 += __expf(w.x); s1 += __expf(w.y);
                s2 += __expf(w.z); s3 += __expf(w.w);
            } else {
                s0 += fexp_poly(w.x); s1 += fexp_poly(w.y);
                s2 += fexp_poly(w.z); s3 += fexp_poly(w.w);
            }
        }
        if (w.x > a0) { a0 = w.x; i0 = e + 0; }
        if (w.y > a1) { a1 = w.y; i1 = e + 1; }
        if (w.z > a2) { a2 = w.z; i2 = e + 2; }
        if (w.w > a3) { a3 = w.w; i3 = e + 3; }
    }
    s = (s0 + s1) + (s2 + s3);
    av = a0; ai = i0;
    amax_comb(av, ai, a1, i1);
    amax_comb(av, ai, a2, i2);
    amax_comb(av, ai, a3, i3);
}

__device__ __forceinline__ void wred(float& s, float& av, int& ai) {
    #pragma unroll
    for (int o = 16; o > 0; o >>= 1) {
        float s2  = __shfl_down_sync(0xffffffffu, s,  o);
        float av2 = __shfl_down_sync(0xffffffffu, av, o);
        int   ai2 = __shfl_down_sync(0xffffffffu, ai, o);
        s += s2;
        amax_comb(av, ai, av2, ai2);
    }
}

__global__ void __launch_bounds__(THREADS, 2) fused_taxanet_kernel(
    const float* __restrict__ y_pred,
    const int*   __restrict__ y_true,
    const float* __restrict__ H,
    float*       __restrict__ out)
{
    const int b    = blockIdx.x;
    const int tid  = threadIdx.x;
    const int warp = tid >> 5;
    const int lane = tid & 31;

    __shared__ float s_s3[8], s_av3[8];
    __shared__ int   s_ai3[8];
    __shared__ float s_s2[4], s_av2[4];
    __shared__ int   s_ai2[4];
    __shared__ float s_s1;
    __shared__ int   s_ai1, s_ai0;
    __shared__ float s_tlogit[4];
    __shared__ int   s_g2abs;
    __shared__ float s_nll1, s_nll2, s_c01, s_c12;
    __shared__ float s_sink[8];

    const float* base = y_pred + (size_t)b * NLEV * CDIM;

    if (warp < 8) {
        // ---- L3 sweep: warps 0-7, 256 lanes, 8 batches ----
        const float4* row4 = reinterpret_cast<const float4*>(base + 3 * CDIM);
        float s, av; int ai;
        accum<2000, 256, 8, true>(row4, tid, s, av, ai);
        wred(s, av, ai);
        if (lane == 0) { s_s3[warp] = s; s_av3[warp] = av; s_ai3[warp] = ai; }
    } else {
        // ---- Small-level subgroup: warps 8-15 (256 threads) ----
        if (warp < 12) {                       // L2: 4 warps
            const float4* row4 = reinterpret_cast<const float4*>(base + 2 * CDIM);
            float s, av; int ai;
            accum<500, 128, 4, true>(row4, tid - 256, s, av, ai);
            wred(s, av, ai);
            if (lane == 0) { s_s2[warp - 8] = s; s_av2[warp - 8] = av; s_ai2[warp - 8] = ai; }
        } else if (warp == 12) {               // L1: 1 warp
            const float4* row4 = reinterpret_cast<const float4*>(base + 1 * CDIM);
            float s, av; int ai;
            accum<100, 32, 4, true>(row4, lane, s, av, ai);
            wred(s, av, ai);
            if (lane == 0) { s_s1 = s; s_ai1 = ai; }
        } else if (warp == 13) {               // L0: 1 warp, argmax only
            const float4* row4 = reinterpret_cast<const float4*>(base);
            float s, av; int ai;
            accum<25, 32, 1, false>(row4, lane, s, av, ai);
            wred(s, av, ai);
            if (lane == 0) { s_ai0 = ai; }
        } else if (warp == 14) {               // target logits
            if (lane < 3) {
                const int jj  = lane + 1;
                const int szs = (jj == 1) ? 400 : (jj == 2) ? 2000 : 8000;
                int tgt = __ldg(&y_true[b * NLEV + jj]);
                tgt = min(max(tgt, 0), szs - 1);
                s_tlogit[jj] = __ldg(base + (size_t)jj * CDIM + tgt);
            }
        }
        // warp 15: nothing yet (helps prefetch below)

        asm volatile("bar.sync 1, 256;" ::: "memory");   // subgroup barrier A

        if (warp == 8) {
            // All 32 lanes redundantly fold L2 + compute nll1/nll2 (no divergence).
            float sum2 = ((s_s2[0] + s_s2[1]) + (s_s2[2] + s_s2[3]));
            float av2  = s_av2[0]; int ai2 = s_ai2[0];
            amax_comb(av2, ai2, s_av2[1], s_ai2[1]);
            amax_comb(av2, ai2, s_av2[2], s_ai2[2]);
            amax_comb(av2, ai2, s_av2[3], s_ai2[3]);
            if (lane == 0) {
                s_g2abs = ai2 + 500;
                s_nll2  = __logf(sum2) - s_tlogit[2];
                s_nll1  = __logf(s_s1) - s_tlogit[1];
            }
        }

        asm volatile("bar.sync 1, 256;" ::: "memory");   // subgroup barrier B

        const int g2a = s_g2abs;
        if (warp == 14) {
            // All lanes load the two known H elements (broadcast); lane 0 stores.
            const int g0a = s_ai0;
            const int g1a = s_ai1 + 100;
            float c01 = __ldg(&H[(size_t)g0a * NTOTAL + g1a]);
            float c12 = __ldg(&H[(size_t)g1a * NTOTAL + g2a]);
            if (lane == 0) { s_c01 = c01; s_c12 = c12; }
        } else {
            // Warps 8-13,15 (224 threads): warm L1 with H[g2][2500..10500)
            // = 250 x 128B lines, overlapped with the still-running L3 sweep.
            int pt = (warp == 15) ? (192 + lane) : ((warp - 8) * 32 + lane);
            float acc = 0.f;
            const float* hrow = H + (size_t)g2a * NTOTAL;
            acc += __ldg(hrow + 2500 + pt * 32);
            if (pt < 26) acc += __ldg(hrow + 2500 + (224 + pt) * 32);
            #pragma unroll
            for (int o = 16; o > 0; o >>= 1)
                acc += __shfl_down_sync(0xffffffffu, acc, o);
            if (lane == 0) s_sink[warp - 8] = acc;   // keep loads live
        }
    }
    __syncthreads();   // single block-wide barrier

    // ---- Warp 0 tail: fold L3 only; H[g2][g3] is an L1 hit ----
    if (warp == 0) {
        float rs = 0.f, rav = -FLT_MAX; int rai = 0x7fffffff;
        if (lane < 8) { rs = s_s3[lane]; rav = s_av3[lane]; rai = s_ai3[lane]; }
        #pragma unroll
        for (int o = 4; o > 0; o >>= 1) {
            float s2  = __shfl_down_sync(0xffffffffu, rs,  o);
            float av2 = __shfl_down_sync(0xffffffffu, rav, o);
            int   ai2 = __shfl_down_sync(0xffffffffu, rai, o);
            if (lane + o < 8) {
                rs += s2;
                amax_comb(rav, rai, av2, ai2);
            }
        }
        if (lane == 0) {
            const int g3abs = rai + 2500;
            float nll3 = __logf(rs) - s_tlogit[3];

            float h23 = __ldg(&H[(size_t)s_g2abs * NTOTAL + g3abs]);  // L1 hit
            float c01 = (s_c01 == 1.0f) ? 1.0f : 0.0f;
            float c12 = (s_c12 == 1.0f) ? 1.0f : 0.0f;
            float c23 = (h23   == 1.0f) ? 1.0f : 0.0f;

            const float E    = 2.7182817459106445f;   // float32(np.e)
            const float invB = 1.0f / (float)BATCH;
            float p = 0.25f * (E * c01 + s_nll1 * invB)
                    + 0.15f * (E * c12 + s_nll2 * invB)
                    + 0.10f * (E * c23 + nll3   * invB);
            p = fmaxf(p, 0.0f);   // mathematically guaranteed; guards fixed-point

            unsigned long long fx =
                (unsigned long long)__float2ll_rn(p * 4294967296.0f);   // * 2^32
            unsigned long long old = atomicAdd(&g_acc, fx + (1ULL << 48));
            if ((old >> 48) == BATCH - 1) {
                unsigned long long tot = (old & 0xFFFFFFFFFFFFULL) + fx;
                out[0] = (float)((double)tot * (1.0 / 4294967296.0));
                g_acc = 0ULL;   // reset for graph replay
            }
        }
    }
}

extern "C" void kernel_launch(void* const* d_in, const int* in_sizes, int n_in,
                              void* d_out, int out_size) {
    const float* y_pred = (const float*)d_in[0];
    const int*   y_true = (const int*)d_in[1];
    const float* H      = (const float*)d_in[2];
    float*       out    = (float*)d_out;

    fused_taxanet_kernel<<<BATCH, THREADS>>>(y_pred, y_true, H, out);
}

// round 15
// speedup vs baseline: 1.0036x; 1.0036x over previous
#include <cuda_runtime.h>
#include <math.h>
#include <float.h>

#define BATCH   256
#define NLEV    4
#define CDIM    8000
#define NTOTAL  10500
#define THREADS 512

// Packed accumulator: bits [0,48) fixed-point sum (x 2^32, all p >= 0),
// bits [48,..) arrival count. Integer adds commute exactly -> deterministic
// result independent of block arrival order. Zero-init; finisher resets it
// so every graph replay starts from zero.
__device__ unsigned long long g_acc = 0ULL;

__device__ __forceinline__ void amax_comb(float& av, int& ai, float av2, int ai2) {
    if (av2 > av || (av2 == av && ai2 < ai)) { av = av2; ai = ai2; }
}

// Exp-sum + argmax over one level's prefix (N4 float4s); ITERS loads issued
// up-front for maximum memory-level parallelism.
template<int N4, int STRIDE, int ITERS, bool NEED_SUM>
__device__ __forceinline__ void accum(const float4* __restrict__ row4, int lt,
                                      float& s, float& av, int& ai) {
    float4 v[ITERS]; int id[ITERS]; bool p[ITERS];
    #pragma unroll
    for (int k = 0; k < ITERS; k++) {
        int idx = lt + k * STRIDE;
        p[k]  = idx < N4;
        id[k] = p[k] ? idx : (N4 - 1);
        v[k]  = __ldg(&row4[id[k]]);
    }
    float s0 = 0.f, s1 = 0.f, s2 = 0.f, s3 = 0.f;
    float a0 = -FLT_MAX, a1 = -FLT_MAX, a2 = -FLT_MAX, a3 = -FLT_MAX;
    int   i0 = 0x7fffffff, i1 = 0x7fffffff, i2 = 0x7fffffff, i3 = 0x7fffffff;
    #pragma unroll
    for (int k = 0; k < ITERS; k++) {
        float4 w = v[k];
        if (!p[k]) { w.x = w.y = w.z = w.w = -FLT_MAX; }   // exp->0, never argmax
        int e = 4 * id[k];
        if (NEED_SUM) {
            s0 += __expf(w.x); s1 += __expf(w.y);
            s2 += __expf(w.z); s3 += __expf(w.w);
        }
        if (w.x > a0) { a0 = w.x; i0 = e + 0; }
        if (w.y > a1) { a1 = w.y; i1 = e + 1; }
        if (w.z > a2) { a2 = w.z; i2 = e + 2; }
        if (w.w > a3) { a3 = w.w; i3 = e + 3; }
    }
    s = (s0 + s1) + (s2 + s3);
    av = a0; ai = i0;
    amax_comb(av, ai, a1, i1);
    amax_comb(av, ai, a2, i2);
    amax_comb(av, ai, a3, i3);
}

__global__ void __launch_bounds__(THREADS, 2) fused_taxanet_kernel(
    const float* __restrict__ y_pred,
    const int*   __restrict__ y_true,
    const float* __restrict__ H,
    float*       __restrict__ out)
{
    const int b    = blockIdx.x;
    const int tid  = threadIdx.x;
    const int warp = tid >> 5;
    const int lane = tid & 31;

    __shared__ float s_s[16], s_av[16];
    __shared__ int   s_ai[16];
    __shared__ float s_tlogit[4];

    const float* base = y_pred + (size_t)b * NLEV * CDIM;

    if (warp == 15) {
        // Prefetch target logits (two dependent trips, hidden by the sweep).
        if (lane < 3) {
            const int jj  = lane + 1;
            const int szs = (jj == 1) ? 400 : (jj == 2) ? 2000 : 8000;
            int tgt = __ldg(&y_true[b * NLEV + jj]);
            tgt = min(max(tgt, 0), szs - 1);
            s_tlogit[jj] = __ldg(base + (size_t)jj * CDIM + tgt);
        }
        if (lane == 0) { s_s[15] = 0.f; s_av[15] = -FLT_MAX; s_ai[15] = 0x7fffffff; }
    } else {
        // Segments: warps [0,8)->L3, [8,12)->L2, [12,14)->L1, [14]->L0
        int j, seg_base;
        if (warp < 8)       { j = 3; seg_base = 0;  }
        else if (warp < 12) { j = 2; seg_base = 8;  }
        else if (warp < 14) { j = 1; seg_base = 12; }
        else                { j = 0; seg_base = 14; }
        const int lt = tid - seg_base * 32;

        const float4* row4 = reinterpret_cast<const float4*>(base + (size_t)j * CDIM);

        float s, av; int ai;
        if (j == 3)      accum<2000, 256, 8, true >(row4, lt, s, av, ai);
        else if (j == 2) accum< 500, 128, 4, true >(row4, lt, s, av, ai);
        else if (j == 1) accum< 100,  64, 2, true >(row4, lt, s, av, ai);
        else             accum<  25,  32, 1, false>(row4, lt, s, av, ai);

        #pragma unroll
        for (int o = 16; o > 0; o >>= 1) {
            float s2  = __shfl_down_sync(0xffffffffu, s,  o);
            float av2 = __shfl_down_sync(0xffffffffu, av, o);
            int   ai2 = __shfl_down_sync(0xffffffffu, ai, o);
            s += s2;
            amax_comb(av, ai, av2, ai2);
        }
        if (lane == 0) { s_s[warp] = s; s_av[warp] = av; s_ai[warp] = ai; }
    }
    __syncthreads();   // the ONLY block-wide barrier

    // Warp 0 finishes the whole block: segmented reduce, H gathers, one atomic.
    if (warp == 0) {
        float rs = 0.f, rav = -FLT_MAX; int rai = 0x7fffffff;
        if (lane < 16) { rs = s_s[lane]; rav = s_av[lane]; rai = s_ai[lane]; }
        const int segsz   = (lane < 8) ? 8 : (lane < 12) ? 4 : (lane < 14) ? 2 : 1;
        const int segbase = (lane < 8) ? 0 : (lane < 12) ? 8 : (lane < 14) ? 12 : 14;
        const int w = lane - segbase;
        #pragma unroll
        for (int o = 4; o > 0; o >>= 1) {
            float s2  = __shfl_down_sync(0xffffffffu, rs,  o);
            float av2 = __shfl_down_sync(0xffffffffu, rav, o);
            int   ai2 = __shfl_down_sync(0xffffffffu, rai, o);
            if (w + o < segsz) {
                rs += s2;
                amax_comb(rav, rai, av2, ai2);
            }
        }
        // Heads: lane0->L3, lane8->L2, lane12->L1, lane14->L0.
        float nllv = 0.f;
        if (lane == 0)       nllv = __logf(rs) - s_tlogit[3];
        else if (lane == 8)  nllv = __logf(rs) - s_tlogit[2];
        else if (lane == 12) nllv = __logf(rs) - s_tlogit[1];

        const unsigned FULL = 0xffffffffu;
        int   g3i = __shfl_sync(FULL, rai, 0);
        int   g2i = __shfl_sync(FULL, rai, 8);
        int   g1i = __shfl_sync(FULL, rai, 12);
        int   g0i = __shfl_sync(FULL, rai, 14);
        float nll3 = __shfl_sync(FULL, nllv, 0);
        float nll2 = __shfl_sync(FULL, nllv, 8);
        float nll1 = __shfl_sync(FULL, nllv, 12);

        if (lane == 0) {
            const int g0 = g0i;
            const int g1 = g1i + 100;
            const int g2 = g2i + 500;
            const int g3 = g3i + 2500;

            // Three independent gathers issue together (MLP).
            float h01 = __ldg(&H[(size_t)g0 * NTOTAL + g1]);
            float h12 = __ldg(&H[(size_t)g1 * NTOTAL + g2]);
            float h23 = __ldg(&H[(size_t)g2 * NTOTAL + g3]);
            float c01 = (h01 == 1.0f) ? 1.0f : 0.0f;
            float c12 = (h12 == 1.0f) ? 1.0f : 0.0f;
            float c23 = (h23 == 1.0f) ? 1.0f : 0.0f;

            const float E    = 2.7182817459106445f;   // float32(np.e)
            const float invB = 1.0f / (float)BATCH;
            float p = 0.25f * (E * c01 + nll1 * invB)
                    + 0.15f * (E * c12 + nll2 * invB)
                    + 0.10f * (E * c23 + nll3 * invB);
            p = fmaxf(p, 0.0f);   // mathematically guaranteed; guards fixed-point

            unsigned long long fx =
                (unsigned long long)__float2ll_rn(p * 4294967296.0f);   // * 2^32
            unsigned long long old = atomicAdd(&g_acc, fx + (1ULL << 48));
            if ((old >> 48) == BATCH - 1) {
                unsigned long long tot = (old & 0xFFFFFFFFFFFFULL) + fx;
                out[0] = (float)((double)tot * (1.0 / 4294967296.0));
                g_acc = 0ULL;   // reset for graph replay
            }
        }
    }
}

extern "C" void kernel_launch(void* const* d_in, const int* in_sizes, int n_in,
                              void* d_out, int out_size) {
    const float* y_pred = (const float*)d_in[0];
    const int*   y_true = (const int*)d_in[1];
    const float* H      = (const float*)d_in[2];
    float*       out    = (float*)d_out;

    fused_taxanet_kernel<<<BATCH, THREADS>>>(y_pred, y_true, H, out);
}

// round 16
// speedup vs baseline: 1.0332x; 1.0295x over previous
#include <cuda_runtime.h>
#include <math.h>
#include <float.h>

#define BATCH   256
#define NLEV    4
#define CDIM    8000
#define NTOTAL  10500
#define THREADS 768

// Packed accumulator: bits [0,48) fixed-point sum (x 2^32, all p >= 0),
// bits [48,..) arrival count. Integer adds commute exactly -> deterministic.
__device__ unsigned long long g_acc = 0ULL;

__device__ __forceinline__ void amax_comb(float& av, int& ai, float av2, int ai2) {
    if (av2 > av || (av2 == av && ai2 < ai)) { av = av2; ai = ai2; }
}

// Exp-sum + argmax over one level's prefix (N4 float4s); ITERS loads issued
// up-front for maximum memory-level parallelism.
template<int N4, int STRIDE, int ITERS, bool NEED_SUM>
__device__ __forceinline__ void accum(const float4* __restrict__ row4, int lt,
                                      float& s, float& av, int& ai) {
    float4 v[ITERS]; int id[ITERS]; bool p[ITERS];
    #pragma unroll
    for (int k = 0; k < ITERS; k++) {
        int idx = lt + k * STRIDE;
        p[k]  = idx < N4;
        id[k] = p[k] ? idx : (N4 - 1);
        v[k]  = __ldg(&row4[id[k]]);
    }
    float s0 = 0.f, s1 = 0.f, s2 = 0.f, s3 = 0.f;
    float a0 = -FLT_MAX, a1 = -FLT_MAX, a2 = -FLT_MAX, a3 = -FLT_MAX;
    int   i0 = 0x7fffffff, i1 = 0x7fffffff, i2 = 0x7fffffff, i3 = 0x7fffffff;
    #pragma unroll
    for (int k = 0; k < ITERS; k++) {
        float4 w = v[k];
        if (!p[k]) { w.x = w.y = w.z = w.w = -FLT_MAX; }   // exp->0, never argmax
        int e = 4 * id[k];
        if (NEED_SUM) {
            s0 += __expf(w.x); s1 += __expf(w.y);
            s2 += __expf(w.z); s3 += __expf(w.w);
        }
        if (w.x > a0) { a0 = w.x; i0 = e + 0; }
        if (w.y > a1) { a1 = w.y; i1 = e + 1; }
        if (w.z > a2) { a2 = w.z; i2 = e + 2; }
        if (w.w > a3) { a3 = w.w; i3 = e + 3; }
    }
    s = (s0 + s1) + (s2 + s3);
    av = a0; ai = i0;
    amax_comb(av, ai, a1, i1);
    amax_comb(av, ai, a2, i2);
    amax_comb(av, ai, a3, i3);
}

__global__ void __launch_bounds__(THREADS, 2) fused_taxanet_kernel(
    const float* __restrict__ y_pred,
    const int*   __restrict__ y_true,
    const float* __restrict__ H,
    float*       __restrict__ out)
{
    const int b    = blockIdx.x;
    const int tid  = threadIdx.x;
    const int warp = tid >> 5;
    const int lane = tid & 31;

    __shared__ float s_s[24], s_av[24];
    __shared__ int   s_ai[24];
    __shared__ float s_tlogit[4];

    const float* base = y_pred + (size_t)b * NLEV * CDIM;

    if (warp == 23) {
        // Prefetch target logits (two dependent trips, hidden by the sweep).
        if (lane < 3) {
            const int jj  = lane + 1;
            const int szs = (jj == 1) ? 400 : (jj == 2) ? 2000 : 8000;
            int tgt = __ldg(&y_true[b * NLEV + jj]);
            tgt = min(max(tgt, 0), szs - 1);
            s_tlogit[jj] = __ldg(base + (size_t)jj * CDIM + tgt);
        }
        if (lane == 0) { s_s[23] = 0.f; s_av[23] = -FLT_MAX; s_ai[23] = 0x7fffffff; }
    } else {
        // Segments: warps [0,16)->L3, [16,20)->L2, [20,22)->L1, [22]->L0
        int j, seg_base;
        if (warp < 16)      { j = 3; seg_base = 0;  }
        else if (warp < 20) { j = 2; seg_base = 16; }
        else if (warp < 22) { j = 1; seg_base = 20; }
        else                { j = 0; seg_base = 22; }
        const int lt = tid - seg_base * 32;

        const float4* row4 = reinterpret_cast<const float4*>(base + (size_t)j * CDIM);

        float s, av; int ai;
        if (j == 3)      accum<2000, 512, 4, true >(row4, lt, s, av, ai);
        else if (j == 2) accum< 500, 128, 4, true >(row4, lt, s, av, ai);
        else if (j == 1) accum< 100,  64, 2, true >(row4, lt, s, av, ai);
        else             accum<  25,  32, 1, false>(row4, lt, s, av, ai);

        #pragma unroll
        for (int o = 16; o > 0; o >>= 1) {
            float s2  = __shfl_down_sync(0xffffffffu, s,  o);
            float av2 = __shfl_down_sync(0xffffffffu, av, o);
            int   ai2 = __shfl_down_sync(0xffffffffu, ai, o);
            s += s2;
            amax_comb(av, ai, av2, ai2);
        }
        if (lane == 0) { s_s[warp] = s; s_av[warp] = av; s_ai[warp] = ai; }
    }
    __syncthreads();   // the ONLY block-wide barrier

    // Warp 0 finishes the whole block: segmented fold of 24 partials,
    // H gathers, one packed atomic.
    if (warp == 0) {
        float rs = 0.f, rav = -FLT_MAX; int rai = 0x7fffffff;
        if (lane < 24) { rs = s_s[lane]; rav = s_av[lane]; rai = s_ai[lane]; }
        // Segments in the 24 slots: L3 [0,16), L2 [16,20), L1 [20,22), L0 [22]
        const int segsz   = (lane < 16) ? 16 : (lane < 20) ? 4 : (lane < 22) ? 2 : 1;
        const int segbase = (lane < 16) ? 0  : (lane < 20) ? 16 : (lane < 22) ? 20 : 22;
        const int w = lane - segbase;
        #pragma unroll
        for (int o = 8; o > 0; o >>= 1) {
            float s2  = __shfl_down_sync(0xffffffffu, rs,  o);
            float av2 = __shfl_down_sync(0xffffffffu, rav, o);
            int   ai2 = __shfl_down_sync(0xffffffffu, rai, o);
            if (w + o < segsz) {
                rs += s2;
                amax_comb(rav, rai, av2, ai2);
            }
        }
        // Heads: lane0->L3, lane16->L2, lane20->L1, lane22->L0.
        float nllv = 0.f;
        if (lane == 0)       nllv = __logf(rs) - s_tlogit[3];
        else if (lane == 16) nllv = __logf(rs) - s_tlogit[2];
        else if (lane == 20) nllv = __logf(rs) - s_tlogit[1];

        const unsigned FULL = 0xffffffffu;
        int   g3i = __shfl_sync(FULL, rai,  0);
        int   g2i = __shfl_sync(FULL, rai, 16);
        int   g1i = __shfl_sync(FULL, rai, 20);
        int   g0i = __shfl_sync(FULL, rai, 22);
        float nll3 = __shfl_sync(FULL, nllv,  0);
        float nll2 = __shfl_sync(FULL, nllv, 16);
        float nll1 = __shfl_sync(FULL, nllv, 20);

        if (lane == 0) {
            const int g0 = g0i;
            const int g1 = g1i + 100;
            const int g2 = g2i + 500;
            const int g3 = g3i + 2500;

            // Three independent gathers issue together (MLP).
            float h01 = __ldg(&H[(size_t)g0 * NTOTAL + g1]);
            float h12 = __ldg(&H[(size_t)g1 * NTOTAL + g2]);
            float h23 = __ldg(&H[(size_t)g2 * NTOTAL + g3]);
            float c01 = (h01 == 1.0f) ? 1.0f : 0.0f;
            float c12 = (h12 == 1.0f) ? 1.0f : 0.0f;
            float c23 = (h23 == 1.0f) ? 1.0f : 0.0f;

            const float E    = 2.7182817459106445f;   // float32(np.e)
            const float invB = 1.0f / (float)BATCH;
            float p = 0.25f * (E * c01 + nll1 * invB)
                    + 0.15f * (E * c12 + nll2 * invB)
                    + 0.10f * (E * c23 + nll3 * invB);
            p = fmaxf(p, 0.0f);   // mathematically guaranteed; guards fixed-point

            unsigned long long fx =
                (unsigned long long)__float2ll_rn(p * 4294967296.0f);   // * 2^32
            unsigned long long old = atomicAdd(&g_acc, fx + (1ULL << 48));
            if ((old >> 48) == BATCH - 1) {
                unsigned long long tot = (old & 0xFFFFFFFFFFFFULL) + fx;
                out[0] = (float)((double)tot * (1.0 / 4294967296.0));
                g_acc = 0ULL;   // reset for graph replay
            }
        }
    }
}

extern "C" void kernel_launch(void* const* d_in, const int* in_sizes, int n_in,
                              void* d_out, int out_size) {
    const float* y_pred = (const float*)d_in[0];
    const int*   y_true = (const int*)d_in[1];
    const float* H      = (const float*)d_in[2];
    float*       out    = (float*)d_out;

    fused_taxanet_kernel<<<BATCH, THREADS>>>(y_pred, y_true, H, out);
}